// round 4
// baseline (speedup 1.0000x reference)
#include <cuda_runtime.h>
#include <cstdint>

// 1x1 conv as GEMM via mma.sync m16n8k8 tf32.
// D[m=hw][n=cout] = sum_k x[k][m] * w[k][n]
// CTA tile 128m x 128n. 8 warps of 64m x 32n (2 m-groups x 4 n-groups).
// B (weight) pre-packed per-lane fragments in SMEM; x via 3-stage cp.async.

#define CIN    128
#define COUT   128
#define HW     16384
#define NTILES 4096
#define GRID   304
#define THREADS 256

#define WF_BYTES   65536              // 16 kstep x 16 ntile x 32 lane x 8B
#define XBUF_BYTES (32 * 128 * 4)     // one 32k x 128m chunk (16KB)
#define NSTAGE 3
#define SMEM_BYTES (WF_BYTES + NSTAGE * XBUF_BYTES)   // 114688

__device__ __forceinline__ uint32_t smem_u32(const void* p) {
    uint32_t a;
    asm("{ .reg .u64 t; cvta.to.shared.u64 t, %1; cvt.u32.u64 %0, t; }" : "=r"(a) : "l"(p));
    return a;
}
__device__ __forceinline__ uint32_t f2tf32(float v) {
    uint32_t u;
    asm("cvt.rna.tf32.f32 %0, %1;" : "=r"(u) : "f"(v));
    return u;
}
__device__ __forceinline__ void cp16(uint32_t dst, const float* src) {
    asm volatile("cp.async.cg.shared.global [%0], [%1], 16;" :: "r"(dst), "l"(src) : "memory");
}
__device__ __forceinline__ uint32_t lds32(uint32_t a) {
    uint32_t v;
    asm volatile("ld.shared.b32 %0, [%1];" : "=r"(v) : "r"(a));
    return v;
}

#define MMA(d, a0, a1, a2, a3, b0, b1)                                         \
    asm volatile("mma.sync.aligned.m16n8k8.row.col.f32.tf32.tf32.f32 "         \
                 "{%0,%1,%2,%3}, {%4,%5,%6,%7}, {%8,%9}, {%0,%1,%2,%3};"       \
                 : "+f"(d[0]), "+f"(d[1]), "+f"(d[2]), "+f"(d[3])              \
                 : "r"(a0), "r"(a1), "r"(a2), "r"(a3), "r"(b0), "r"(b1))

// issue DMA for global chunk g (tile g>>2, k-range (g&3)*32 .. +31)
__device__ __forceinline__ void issue_chunk(const float* __restrict__ x,
                                            uint32_t xs, int g, int tid, int bid)
{
    const int t   = bid + (g >> 2) * GRID;
    const int b   = t >> 7;
    const int hw0 = (t & 127) << 7;
    const int kb  = (g & 3) * 32;
    const float* xb = x + (size_t)b * CIN * HW + (size_t)kb * HW + hw0;
    const uint32_t dstb = xs + (uint32_t)(g % NSTAGE) * XBUF_BYTES;
    const int krow = tid >> 5;            // 0..7
    const int m4   = (tid & 31) * 4;      // 0..124
    #pragma unroll
    for (int p = 0; p < 4; p++) {
        const int k = p * 8 + krow;       // 0..31
        const uint32_t pm = (uint32_t)m4 ^ (uint32_t)((k & 3) << 3);
        cp16(dstb + (uint32_t)(k * 128 + pm) * 4, xb + (size_t)k * HW + m4);
    }
    asm volatile("cp.async.commit_group;" ::: "memory");
}

__global__ __launch_bounds__(THREADS, 2)
void conv1x1_mma_tf32_v2(const float* __restrict__ x,
                         const float* __restrict__ w,
                         float* __restrict__ out)
{
    extern __shared__ char smem[];
    const uint32_t sb = smem_u32(smem);
    const uint32_t wf = sb;               // packed B fragments
    const uint32_t xs = sb + WF_BYTES;    // x chunk buffers (x3)

    const int tid  = threadIdx.x;
    const int lane = tid & 31;
    const int wid  = tid >> 5;
    const int wm   = (wid & 1) * 64;      // warp m offset (0 or 64)
    const int wnt  = (wid >> 1) * 4;      // warp ntile offset (0,4,8,12)

    const int g = lane >> 2;              // groupID (0..7)
    const int c = lane & 3;               // threadID_in_group (0..3)
    const int bid = blockIdx.x;

    const int ntl = (NTILES - bid + GRID - 1) / GRID;   // local tile count
    const int nch = ntl * 4;                             // local chunk count

    // ---- prologue: start DMA of first two chunks ----
    issue_chunk(x, xs, 0, tid, bid);
    if (nch > 1) issue_chunk(x, xs, 1, tid, bid);

    // ---- pack weights into per-lane B fragment layout (tf32-converted) ----
    // Wf[s][ntile][lane] = { w[s*8 + c][ntile*8 + g], w[s*8 + c + 4][same n] }
    for (int idx = tid; idx < 8192; idx += THREADS) {
        const int s  = idx >> 9;
        const int r  = idx & 511;
        const int tn = r >> 5;
        const int l  = r & 31;
        const int k0 = s * 8 + (l & 3);
        const int n  = tn * 8 + (l >> 2);
        const uint32_t b0 = f2tf32(w[k0 * COUT + n]);
        const uint32_t b1 = f2tf32(w[(k0 + 4) * COUT + n]);
        asm volatile("st.shared.v2.b32 [%0], {%1,%2};"
                     :: "r"(wf + (uint32_t)idx * 8), "r"(b0), "r"(b1) : "memory");
    }

    float acc[4][4][4];

    #pragma unroll 1
    for (int gch = 0; gch < nch; gch++) {
        // chunk gch data ready (≤1 younger group still pending)
        asm volatile("cp.async.wait_group 1;" ::: "memory");
        __syncthreads();   // data visible to all; all warps done reading buf[(gch+2)%3]

        if (gch + 2 < nch) issue_chunk(x, xs, gch + 2, tid, bid);

        if ((gch & 3) == 0) {
            #pragma unroll
            for (int mt = 0; mt < 4; mt++)
                #pragma unroll
                for (int nt = 0; nt < 4; nt++)
                    #pragma unroll
                    for (int j = 0; j < 4; j++)
                        acc[mt][nt][j] = 0.0f;
        }

        // ---- compute 4 k-steps (k8 each) from buf[gch%3] ----
        const uint32_t xbuf = xs + (uint32_t)(gch % NSTAGE) * XBUF_BYTES;
        #pragma unroll
        for (int s2 = 0; s2 < 4; s2++) {
            const int s  = (gch & 3) * 4 + s2;   // global kstep 0..15
            const int kl = s2 * 8 + c;

            // A fragments (conflict-free swizzled LDS)
            uint32_t a[4][4];
            #pragma unroll
            for (int mt = 0; mt < 4; mt++) {
                const uint32_t m0 = (uint32_t)(wm + 16 * mt + g);
                const uint32_t p0 = m0 ^ (uint32_t)(c << 3);
                const uint32_t ad0 = xbuf + (uint32_t)(kl * 128 + p0) * 4;
                const uint32_t ad1 = ad0 ^ 32u;          // m + 8
                a[mt][0] = f2tf32(__uint_as_float(lds32(ad0)));
                a[mt][1] = f2tf32(__uint_as_float(lds32(ad1)));
                a[mt][2] = f2tf32(__uint_as_float(lds32(ad0 + 2048u)));  // k + 4
                a[mt][3] = f2tf32(__uint_as_float(lds32(ad1 + 2048u)));
            }

            // B fragments (one LDS.64 each)
            uint32_t bf[4][2];
            #pragma unroll
            for (int nt = 0; nt < 4; nt++) {
                const uint32_t ba = wf + (uint32_t)(((s * 16 + wnt + nt) * 32 + lane)) * 8;
                asm volatile("ld.shared.v2.b32 {%0,%1}, [%2];"
                             : "=r"(bf[nt][0]), "=r"(bf[nt][1]) : "r"(ba));
            }

            #pragma unroll
            for (int mt = 0; mt < 4; mt++)
                #pragma unroll
                for (int nt = 0; nt < 4; nt++)
                    MMA(acc[mt][nt], a[mt][0], a[mt][1], a[mt][2], a[mt][3],
                        bf[nt][0], bf[nt][1]);
        }

        // ---- epilogue after last chunk of a tile ----
        if ((gch & 3) == 3) {
            const int t   = bid + (gch >> 2) * GRID;
            const int b   = t >> 7;
            const int hw0 = (t & 127) << 7;
            float* ob = out + (size_t)b * COUT * HW + hw0;
            #pragma unroll
            for (int mt = 0; mt < 4; mt++) {
                const int m0 = wm + 16 * mt + g;
                #pragma unroll
                for (int nt = 0; nt < 4; nt++) {
                    const int n0 = (wnt + nt) * 8 + 2 * c;
                    ob[(size_t)n0 * HW + m0]           = acc[mt][nt][0];
                    ob[(size_t)(n0 + 1) * HW + m0]     = acc[mt][nt][1];
                    ob[(size_t)n0 * HW + m0 + 8]       = acc[mt][nt][2];
                    ob[(size_t)(n0 + 1) * HW + m0 + 8] = acc[mt][nt][3];
                }
            }
        }
    }
}

extern "C" void kernel_launch(void* const* d_in, const int* in_sizes, int n_in,
                              void* d_out, int out_size)
{
    const float* x   = (const float*)d_in[0];   // (32, 128, 128, 128) fp32
    const float* w   = (const float*)d_in[1];   // (128, 128) fp32
    float*       out = (float*)d_out;

    cudaFuncSetAttribute(conv1x1_mma_tf32_v2,
                         cudaFuncAttributeMaxDynamicSharedMemorySize, SMEM_BYTES);
    conv1x1_mma_tf32_v2<<<GRID, THREADS, SMEM_BYTES>>>(x, w, out);
}